// round 9
// baseline (speedup 1.0000x reference)
#include <cuda_runtime.h>
#include <math.h>

#define Nn   8
#define Cc   64
#define Hh   128
#define Ww   128
#define HW   (Hh * Ww)          // 16384
#define TOT  (Nn * Cc * HW)     // 8388608
#define CCK  8                  // ci chunk staged in smem
#define TILE 16

__device__ float  g_y[TOT];
__device__ double g_sum[Cc];
__device__ double g_sq[Cc];
__device__ float  g_a[Cc];
__device__ float  g_b[Cc];
__device__ float  g_sw[Cc];     // per-co weight sum: sum_{ci,k} w[co][ci][k]

// ---------------------------------------------------------------------------
// Pass 0: zero accumulators + precompute per-co weight sums
// ---------------------------------------------------------------------------
__global__ void k0_pre(const float* __restrict__ wgt) {
    int t = threadIdx.x;
    if (t < Cc) {
        g_sum[t] = 0.0; g_sq[t] = 0.0;
        float s = 0.0f;
        const float* wp = wgt + t * Cc * 9;   // [co][ci][k] contiguous
        for (int i = 0; i < Cc * 9; i++) s += wp[i];
        g_sw[t] = s;
    }
}

// ---------------------------------------------------------------------------
// Pass 1: adder2d + residual -> g_y, per-channel sum/sumsq (double).
// 256 threads = 16x16 pixel tile, 1 pixel/thread, 64 fp32 accumulators.
//
// Pipe-balance trick:  -sum|x-w| = 2*sum min(x,w) - sum x - sum w.
// Hot loop per element = 1 FMNMX (alu pipe) + 1 FADD (fma pipe) -> dual-pipe
// 1 instr/cyc issue instead of 2 fma-pipe ops at 0.5/cyc.
// sum x is a per-pixel box sum (64x amortized); sum w precomputed in k0.
// Zero padding is exact: x=0 gives w - 2*min(0,w) = |w|.
// ---------------------------------------------------------------------------
__global__ __launch_bounds__(256, 2)
void k1_adder(const float* __restrict__ x, const float* __restrict__ wgt) {
    __shared__ float xs[CCK][18][18];
    __shared__ __align__(16) float wt[CCK][Cc][12];  // 9 used, pad 12
    __shared__ double ssum[Cc];
    __shared__ double ssq[Cc];
    __shared__ float  sw_sh[Cc];

    const int n   = blockIdx.z;
    const int ty0 = blockIdx.y * TILE;
    const int tx0 = blockIdx.x * TILE;
    const int tid = threadIdx.x;
    const int tr  = tid >> 4;
    const int tc  = tid & 15;

    if (tid < Cc) sw_sh[tid] = g_sw[tid];

    float acc[Cc];                 // sum of min(x,w) per co
#pragma unroll
    for (int i = 0; i < Cc; i++) acc[i] = 0.0f;
    float sx = 0.0f;               // box sum of x over all taps, all ci

    for (int cb = 0; cb < Cc; cb += CCK) {
        __syncthreads();
        // stage x halo tile
        for (int i = tid; i < CCK * 18 * 18; i += 256) {
            int ci = i / 324, r = (i / 18) % 18, c = i % 18;
            int gh = ty0 - 1 + r, gw = tx0 - 1 + c;
            float v = 0.0f;
            if ((unsigned)gh < 128u && (unsigned)gw < 128u)
                v = x[((n * Cc + cb + ci) * Hh + gh) * Ww + gw];
            xs[ci][r][c] = v;
        }
        // stage weights
        for (int i = tid; i < CCK * Cc * 9; i += 256) {
            int ci  = i / (Cc * 9);
            int rem = i % (Cc * 9);
            int co  = rem / 9, k = rem % 9;
            wt[ci][co][k] = wgt[(co * Cc + cb + ci) * 9 + k];
        }
        __syncthreads();

#pragma unroll 1
        for (int ci = 0; ci < CCK; ci++) {
            float xv[9];
#pragma unroll
            for (int kh = 0; kh < 3; kh++)
#pragma unroll
                for (int kw = 0; kw < 3; kw++)
                    xv[kh * 3 + kw] = xs[ci][tr + kh][tc + kw];

            // per-pixel box sum (pairwise, short dep chain)
            sx += (((xv[0] + xv[1]) + (xv[2] + xv[3])) +
                   ((xv[4] + xv[5]) + (xv[6] + xv[7]))) + xv[8];

#pragma unroll
            for (int co = 0; co < Cc; co++) {     // FULL unroll: acc[] in regs
                const float4* wv = reinterpret_cast<const float4*>(&wt[ci][co][0]);
                float4 wa = wv[0];                // k = 0..3
                float4 wb = wv[1];                // k = 4..7
                float  w8 = wt[ci][co][8];
                float a = acc[co];
                a += fminf(xv[0], wa.x);          // FMNMX (alu) + FADD (fma)
                a += fminf(xv[1], wa.y);
                a += fminf(xv[2], wa.z);
                a += fminf(xv[3], wa.w);
                a += fminf(xv[4], wb.x);
                a += fminf(xv[5], wb.y);
                a += fminf(xv[6], wb.z);
                a += fminf(xv[7], wb.w);
                a += fminf(xv[8], w8);
                acc[co] = a;
            }
        }
    }

    // ---- epilogue: combine identity, residual, y store, per-channel stats
    __syncthreads();
    if (tid < Cc) { ssum[tid] = 0.0; ssq[tid] = 0.0; }
    __syncthreads();

    const int h    = ty0 + tr;
    const int w    = tx0 + tc;
    const int lane = tid & 31;
    const int pixb = n * Cc * HW + h * Ww + w;

#pragma unroll
    for (int co = 0; co < Cc; co++) {
        // adder out = 2*sum_min - sum_x - sum_w ; then residual add
        float y = fmaf(2.0f, acc[co], -sx - sw_sh[co]) + x[pixb + co * HW];
        g_y[pixb + co * HW] = y;

        float s = y, q = y * y;
#pragma unroll
        for (int off = 16; off; off >>= 1) {
            s += __shfl_xor_sync(0xffffffffu, s, off);
            q += __shfl_xor_sync(0xffffffffu, q, off);
        }
        if (lane == 0) {
            atomicAdd(&ssum[co], (double)s);
            atomicAdd(&ssq[co],  (double)q);
        }
    }
    __syncthreads();
    if (tid < Cc) {
        atomicAdd(&g_sum[tid], ssum[tid]);
        atomicAdd(&g_sq[tid],  ssq[tid]);
    }
}

// ---------------------------------------------------------------------------
__global__ void k2_stats(const float* __restrict__ gamma,
                         const float* __restrict__ beta) {
    int c = threadIdx.x;
    if (c < Cc) {
        const double cnt = (double)(Nn * HW);
        double mean = g_sum[c] / cnt;
        double var  = g_sq[c] / cnt - mean * mean;
        float inv   = (float)(1.0 / sqrt(var + 1e-5));
        float a     = gamma[c] * inv;
        g_a[c] = a;
        g_b[c] = beta[c] - (float)mean * a;
    }
}

// ---------------------------------------------------------------------------
__global__ void k3_out(float* __restrict__ out, const float* __restrict__ alpha) {
    const float al = *alpha;
    int i4 = blockIdx.x * blockDim.x + threadIdx.x;
    if (i4 < TOT / 4) {
        int i = i4 * 4;
        int c = (i >> 14) & 63;                       // HW = 2^14
        float a = g_a[c], b = g_b[c];
        float4 yv = *reinterpret_cast<const float4*>(&g_y[i]);
        float t0 = yv.x * a + b;
        float t1 = yv.y * a + b;
        float t2 = yv.z * a + b;
        float t3 = yv.w * a + b;
        float4 ov;
        if (al == 1.0f) {
            ov = make_float4(t0, t1, t2, t3);   // sign(t)*(|t|+1e-12) == t to 1e-12
        } else {
            float r0 = powf(fabsf(t0) + 1e-12f, al);
            float r1 = powf(fabsf(t1) + 1e-12f, al);
            float r2 = powf(fabsf(t2) + 1e-12f, al);
            float r3 = powf(fabsf(t3) + 1e-12f, al);
            ov.x = (t0 > 0.0f) ? r0 : ((t0 < 0.0f) ? -r0 : 0.0f);
            ov.y = (t1 > 0.0f) ? r1 : ((t1 < 0.0f) ? -r1 : 0.0f);
            ov.z = (t2 > 0.0f) ? r2 : ((t2 < 0.0f) ? -r2 : 0.0f);
            ov.w = (t3 > 0.0f) ? r3 : ((t3 < 0.0f) ? -r3 : 0.0f);
        }
        *reinterpret_cast<float4*>(&out[i]) = ov;
    }
}

// ---------------------------------------------------------------------------
extern "C" void kernel_launch(void* const* d_in, const int* in_sizes, int n_in,
                              void* d_out, int out_size) {
    const float* x     = (const float*)d_in[0];
    const float* wgt   = (const float*)d_in[1];
    const float* gamma = (const float*)d_in[2];
    const float* beta  = (const float*)d_in[3];
    const float* alpha = (const float*)d_in[4];
    float* out = (float*)d_out;

    k0_pre<<<1, 64>>>(wgt);
    dim3 grid(Ww / TILE, Hh / TILE, Nn);   // 8 x 8 x 8
    k1_adder<<<grid, 256>>>(x, wgt);
    k2_stats<<<1, 64>>>(gamma, beta);
    k3_out<<<(TOT / 4 + 255) / 256, 256>>>(out, alpha);
}